// round 17
// baseline (speedup 1.0000x reference)
#include <cuda_runtime.h>
#include <cuda_bf16.h>
#include <cuda_fp16.h>
#include <cstdint>

#define Bn   64
#define Tn   512
#define DIn  512
#define Hn   1024
#define G4   4096
#define BT   (Bn * Tn)
#define NCTA 128

// ---------------- device globals (no runtime allocation) ----------------
__device__ __nv_bfloat16 g_hhi[2][Bn * Hn];       // h split-high, double buffered
__device__ __nv_bfloat16 g_hlo[2][Bn * Hn];       // h split-low
__device__ __half g_xhi[(size_t)BT * DIn];        // inputs fp16 split-high
__device__ __half g_xlo[(size_t)BT * DIn];        // inputs fp16 split-low
__device__ unsigned g_cnt;
__device__ volatile unsigned g_gen;

__device__ __forceinline__ void grid_sync() {
    __threadfence();
    __syncthreads();
    if (threadIdx.x == 0) {
        unsigned g = g_gen;
        if (atomicAdd(&g_cnt, 1u) == NCTA - 1) {
            g_cnt = 0;
            __threadfence();
            g_gen = g + 1;
        } else {
            while (g_gen == g) { }
            __threadfence();
        }
    }
    __syncthreads();
}

// ---------------- mma.sync helpers (standard PTX, sm_80+) ----------------
__device__ __forceinline__ uint32_t smem_u32(const void* p) {
    uint32_t a;
    asm("{ .reg .u64 t; cvta.to.shared.u64 t, %1; cvt.u32.u64 %0, t; }" : "=r"(a) : "l"(p));
    return a;
}
__device__ __forceinline__ void ldsm4(uint32_t addr, uint32_t r[4]) {
    asm volatile("ldmatrix.sync.aligned.m8n8.x4.shared.b16 {%0,%1,%2,%3}, [%4];"
                 : "=r"(r[0]), "=r"(r[1]), "=r"(r[2]), "=r"(r[3]) : "r"(addr));
}
__device__ __forceinline__ void mma_bf(float* d, const uint32_t* a, uint32_t b0, uint32_t b1) {
    asm volatile("mma.sync.aligned.m16n8k16.row.col.f32.bf16.bf16.f32 "
                 "{%0,%1,%2,%3}, {%4,%5,%6,%7}, {%8,%9}, {%0,%1,%2,%3};"
                 : "+f"(d[0]), "+f"(d[1]), "+f"(d[2]), "+f"(d[3])
                 : "r"(a[0]), "r"(a[1]), "r"(a[2]), "r"(a[3]), "r"(b0), "r"(b1));
}
__device__ __forceinline__ void mma_fp(float* d, const uint32_t* a, uint32_t b0, uint32_t b1) {
    asm volatile("mma.sync.aligned.m16n8k16.row.col.f32.f16.f16.f32 "
                 "{%0,%1,%2,%3}, {%4,%5,%6,%7}, {%8,%9}, {%0,%1,%2,%3};"
                 : "+f"(d[0]), "+f"(d[1]), "+f"(d[2]), "+f"(d[3])
                 : "r"(a[0]), "r"(a[1]), "r"(a[2]), "r"(a[3]), "r"(b0), "r"(b1));
}
__device__ __forceinline__ void cpasync16(uint32_t s, const void* g) {
    asm volatile("cp.async.cg.shared.global [%0], [%1], 16;" :: "r"(s), "l"(g) : "memory");
}
#define CP_COMMIT() asm volatile("cp.async.commit_group;" ::: "memory")
#define CP_WAIT0()  asm volatile("cp.async.wait_group 0;" ::: "memory")

// ---------------------------------------------------------------------------
// Kernel 0: inputs fp32 -> fp16 hi/lo split
// ---------------------------------------------------------------------------
__global__ __launch_bounds__(256) void xsplit_kernel(
    const float* __restrict__ src, __half* __restrict__ hi,
    __half* __restrict__ lo, int n4)
{
    int i = blockIdx.x * blockDim.x + threadIdx.x;
    if (i >= n4) return;
    float4 v = ((const float4*)src)[i];
    __half h0 = __float2half_rn(v.x);
    __half h1 = __float2half_rn(v.y);
    __half h2 = __float2half_rn(v.z);
    __half h3 = __float2half_rn(v.w);
    __half l0 = __float2half_rn(v.x - __half2float(h0));
    __half l1 = __float2half_rn(v.y - __half2float(h1));
    __half l2 = __float2half_rn(v.z - __half2float(h2));
    __half l3 = __float2half_rn(v.w - __half2float(h3));
    ushort4 vh = make_ushort4(__half_as_ushort(h0), __half_as_ushort(h1),
                              __half_as_ushort(h2), __half_as_ushort(h3));
    ushort4 vl = make_ushort4(__half_as_ushort(l0), __half_as_ushort(l1),
                              __half_as_ushort(l2), __half_as_ushort(l3));
    ((ushort4*)hi)[i] = vh;
    ((ushort4*)lo)[i] = vl;
}

// ---------------------------------------------------------------------------
// Fused persistent LSTM: gates = [h, x] @ [W_hh ; W_ih]^T + bias, per step.
// 128 CTAs x 256 threads, 1 CTA/SM. CTA owns 32 gate rows (8 h-indices).
// 24 k64-chunks/step: 0-15 = h (bf16 Ootomo 3-term vs W_hh hi/lo in smem),
// 16-23 = x (fp16 2-term: x_hi/x_lo vs single-fp16 W_ih in smem).
// Staging: 2-stage cp.async ring, one __syncthreads per chunk.
//
// smem layout (bytes):
//   W_hh hi : 32 x 2064              [0      .. 66048)
//   W_hh lo : 32 x 2064              [66048  .. 132096)
//   W_ih    : 32 x 1040 fp16         [132096 .. 165376)
//   staging : 2 buf x 2 spl x 64x144 [165376 .. 202240)
//   gbuf    : 64 x 32 f32            [202240 .. 210432)
//   c_s     : 512 f32                [210432 .. 212480)
//   bias_s  : 32 f32                 [212480 .. 212608)
// All row strides ≡ 16 (mod 128): conflict-free ldmatrix.
// ---------------------------------------------------------------------------
#define WROW   2064
#define WSZ    (32 * WROW)            // 66048
#define WIROW  1040
#define WISZ   (32 * WIROW)           // 33280
#define SROW   144
#define SSPL   (64 * SROW)            // 9216
#define SM_WHH 0
#define SM_WIH (2 * WSZ)              // 132096
#define SM_STG (SM_WIH + WISZ)        // 165376
#define SM_GBUF (SM_STG + 4 * SSPL)   // 202240
#define SM_CS   (SM_GBUF + 8192)      // 210432
#define SM_BIAS (SM_CS + 2048)        // 212480
#define SM_TOTAL (SM_BIAS + 128)      // 212608

__global__ __launch_bounds__(256, 1) void lstm_fused_kernel(
    const float* __restrict__ W_hh, const float* __restrict__ W_ih,
    const float* __restrict__ b_ih, const float* __restrict__ b_hh,
    const int* __restrict__ length, float* __restrict__ out)
{
    extern __shared__ char smem[];
    const uint32_t sb = smem_u32(smem);
    __shared__ int len_s[Bn];

    const int tid   = threadIdx.x;
    const int wid   = tid >> 5;
    const int lane  = tid & 31;
    const int cta   = blockIdx.x;
    const int jbase = cta * 8;

    float* gbuf   = (float*)(smem + SM_GBUF);
    float* c_s    = (float*)(smem + SM_CS);
    float* bias_s = (float*)(smem + SM_BIAS);

    // ---- init: W_hh slice -> bf16 hi/lo in smem ----
    {
        const int n    = tid >> 3;                       // 0..31 gate row
        const int grow = ((n >> 3) << 10) + jbase + (n & 7);
        const int cb   = (tid & 7) * 128;
        const float* wrow = W_hh + (size_t)grow * Hn + cb;
        char* whi = smem + SM_WHH + n * WROW + cb * 2;
        char* wlo = whi + WSZ;
        for (int k4 = 0; k4 < 128; k4 += 4) {
            float4 w = *(const float4*)(wrow + k4);
            __nv_bfloat16 h0 = __float2bfloat16(w.x);
            __nv_bfloat16 h1 = __float2bfloat16(w.y);
            __nv_bfloat16 h2 = __float2bfloat16(w.z);
            __nv_bfloat16 h3 = __float2bfloat16(w.w);
            __nv_bfloat16 l0 = __float2bfloat16(w.x - __bfloat162float(h0));
            __nv_bfloat16 l1 = __float2bfloat16(w.y - __bfloat162float(h1));
            __nv_bfloat16 l2 = __float2bfloat16(w.z - __bfloat162float(h2));
            __nv_bfloat16 l3 = __float2bfloat16(w.w - __bfloat162float(h3));
            ushort4 vh = make_ushort4(__bfloat16_as_ushort(h0), __bfloat16_as_ushort(h1),
                                      __bfloat16_as_ushort(h2), __bfloat16_as_ushort(h3));
            ushort4 vl = make_ushort4(__bfloat16_as_ushort(l0), __bfloat16_as_ushort(l1),
                                      __bfloat16_as_ushort(l2), __bfloat16_as_ushort(l3));
            *(ushort4*)(whi + k4 * 2) = vh;
            *(ushort4*)(wlo + k4 * 2) = vl;
        }
    }
    // ---- init: W_ih slice -> single fp16 in smem ----
    {
        const int n    = tid >> 3;
        const int grow = ((n >> 3) << 10) + jbase + (n & 7);
        const int cb   = (tid & 7) * 64;
        const float* wrow = W_ih + (size_t)grow * DIn + cb;
        char* wi = smem + SM_WIH + n * WIROW + cb * 2;
        for (int k4 = 0; k4 < 64; k4 += 4) {
            float4 w = *(const float4*)(wrow + k4);
            ushort4 v = make_ushort4(
                __half_as_ushort(__float2half_rn(w.x)),
                __half_as_ushort(__float2half_rn(w.y)),
                __half_as_ushort(__float2half_rn(w.z)),
                __half_as_ushort(__float2half_rn(w.w)));
            *(ushort4*)(wi + k4 * 2) = v;
        }
    }
    if (tid < 32) {
        const int grow = ((tid >> 3) << 10) + jbase + (tid & 7);
        bias_s[tid] = b_ih[grow] + b_hh[grow];
    }
    for (int i = tid; i < 512; i += 256) c_s[i] = 0.f;
    for (int i = tid; i < 512; i += 256) {
        int b = i >> 3, jj = i & 7;
        g_hhi[0][b * Hn + jbase + jj] = __float2bfloat16(0.f);
        g_hlo[0][b * Hn + jbase + jj] = __float2bfloat16(0.f);
    }
    if (tid < Bn) len_s[tid] = length[tid];
    grid_sync();   // h0, splits, smem W resident

    // ---- warp tile mapping (proven constants) ----
    const int mt = wid & 3;            // m-tile: rows mt*16
    const int nh = wid >> 2;           // n-half: cols nh*16
    const int qr = lane >> 3;
    const int lr8 = lane & 7;
    const uint32_t arow_off  = (uint32_t)((mt * 16 + lr8 + (qr & 1) * 8) * SROW + (qr >> 1) * 16);
    const uint32_t brow_off  = (uint32_t)((nh * 16 + lr8 + (qr >> 1) * 8) * WROW + (qr & 1) * 16);
    const uint32_t brow_offx = (uint32_t)((nh * 16 + lr8 + (qr >> 1) * 8) * WIROW + (qr & 1) * 16);

    // ---- staging mapping: thread -> (batch row, 16-elem segment) ----
    const int srow = tid >> 2;             // 0..63 batch
    const int seg  = (tid & 3) * 16;       // element offset in k64 chunk
    const uint32_t s_off = (uint32_t)(srow * SROW + seg * 2);

    int p = 0;

    for (int t = 0; t < Tn; t++) {
        // ---- chunk stager: c<16 -> h (bf16), else -> x (fp16) ----
        auto stage = [&](int c) {
            const uint32_t sh = sb + SM_STG + (uint32_t)((c & 1) * 2 * SSPL) + s_off;
            const uint32_t sl = sh + SSPL;
            if (c < 16) {
                const __nv_bfloat16* ph = g_hhi[p] + (size_t)srow * Hn + c * 64 + seg;
                const __nv_bfloat16* pl = g_hlo[p] + (size_t)srow * Hn + c * 64 + seg;
                cpasync16(sh, ph);      cpasync16(sh + 16, ph + 8);
                cpasync16(sl, pl);      cpasync16(sl + 16, pl + 8);
            } else {
                const size_t xb = ((size_t)(srow * Tn + t)) * DIn + (c - 16) * 64 + seg;
                const __half* ph = g_xhi + xb;
                const __half* pl = g_xlo + xb;
                cpasync16(sh, ph);      cpasync16(sh + 16, ph + 8);
                cpasync16(sl, pl);      cpasync16(sl + 16, pl + 8);
            }
        };

        float d0a[4] = {0.f, 0.f, 0.f, 0.f};
        float d0b[4] = {0.f, 0.f, 0.f, 0.f};
        float d1a[4] = {0.f, 0.f, 0.f, 0.f};
        float d1b[4] = {0.f, 0.f, 0.f, 0.f};

        stage(0);
        CP_COMMIT();

        for (int c = 0; c < 24; c++) {
            CP_WAIT0();                 // chunk c landed (this thread's group)
            __syncthreads();            // visible to all; buf (c+1)&1 free
            if (c < 23) { stage(c + 1); CP_COMMIT(); }

            const uint32_t a_hi = sb + SM_STG + (uint32_t)((c & 1) * 2 * SSPL) + arow_off;
            const uint32_t a_lo = a_hi + SSPL;
            if (c < 16) {
                const uint32_t b_hi = sb + SM_WHH + brow_off + (uint32_t)(c * 128);
                const uint32_t b_lo = b_hi + WSZ;
#pragma unroll
                for (int kk = 0; kk < 4; kk++) {
                    uint32_t ah[4], al[4], bh[4], bl[4];
                    ldsm4(a_hi + kk * 32, ah);
                    ldsm4(a_lo + kk * 32, al);
                    ldsm4(b_hi + kk * 32, bh);
                    ldsm4(b_lo + kk * 32, bl);
                    mma_bf(d0a, ah, bh[0], bh[1]); mma_bf(d1a, ah, bh[2], bh[3]);
                    mma_bf(d0b, ah, bl[0], bl[1]); mma_bf(d1b, ah, bl[2], bl[3]);
                    mma_bf(d0b, al, bh[0], bh[1]); mma_bf(d1b, al, bh[2], bh[3]);
                }
            } else {
                const uint32_t bw = sb + SM_WIH + brow_offx + (uint32_t)((c - 16) * 128);
#pragma unroll
                for (int kk = 0; kk < 4; kk++) {
                    uint32_t xh[4], xl[4], bwf[4];
                    ldsm4(a_hi + kk * 32, xh);
                    ldsm4(a_lo + kk * 32, xl);
                    ldsm4(bw + kk * 32, bwf);
                    mma_fp(d0a, xh, bwf[0], bwf[1]); mma_fp(d1a, xh, bwf[2], bwf[3]);
                    mma_fp(d0b, xl, bwf[0], bwf[1]); mma_fp(d1b, xl, bwf[2], bwf[3]);
                }
            }
        }

        // ---- scatter D frags to gbuf[64][32] ----
        {
            const int gr = mt * 16 + (lane >> 2);
            const int gc = nh * 16 + (lane & 3) * 2;
            *(float2*)&gbuf[gr * 32 + gc]           = make_float2(d0a[0] + d0b[0], d0a[1] + d0b[1]);
            *(float2*)&gbuf[(gr + 8) * 32 + gc]     = make_float2(d0a[2] + d0b[2], d0a[3] + d0b[3]);
            *(float2*)&gbuf[gr * 32 + gc + 8]       = make_float2(d1a[0] + d1b[0], d1a[1] + d1b[1]);
            *(float2*)&gbuf[(gr + 8) * 32 + gc + 8] = make_float2(d1a[2] + d1b[2], d1a[3] + d1b[3]);
        }
        __syncthreads();

        // ---- epilogue: 512 cells (b, jj) over 256 threads ----
#pragma unroll
        for (int cc = 0; cc < 2; cc++) {
            int cell = cc * 256 + tid;
            int b  = cell >> 3;
            int jj = cell & 7;
            float gi = gbuf[b * 32 +      jj] + bias_s[jj];
            float gf = gbuf[b * 32 +  8 + jj] + bias_s[8 + jj];
            float gg = gbuf[b * 32 + 16 + jj] + bias_s[16 + jj];
            float go = gbuf[b * 32 + 24 + jj] + bias_s[24 + jj];
            float co = c_s[cell];
            float si = 1.f / (1.f + __expf(-gi));
            float sf = 1.f / (1.f + __expf(-gf));
            float so = 1.f / (1.f + __expf(-go));
            float tg = tanhf(gg);
            float cn = sf * co + si * tg;
            float hn = so * tanhf(cn);
            c_s[cell] = cn;

            size_t ob = ((size_t)(b * Tn + t)) * Hn + jbase + jj;
            out[ob] = hn;                                   // hs
            out[(size_t)BT * Hn + ob] = cn;                 // cs

            __nv_bfloat16 hh = __float2bfloat16(hn);
            __nv_bfloat16 hl = __float2bfloat16(hn - __bfloat162float(hh));
            g_hhi[p ^ 1][b * Hn + jbase + jj] = hh;
            g_hlo[p ^ 1][b * Hn + jbase + jj] = hl;

            if (t == len_s[b] - 1) {                        // h_last / c_last
                out[(size_t)2 * BT * Hn + (size_t)b * Hn + jbase + jj] = hn;
                out[(size_t)2 * BT * Hn + (size_t)Bn * Hn + (size_t)b * Hn + jbase + jj] = cn;
            }
        }
        grid_sync();
        p ^= 1;
    }
}

// ---------------------------------------------------------------------------
extern "C" void kernel_launch(void* const* d_in, const int* in_sizes, int n_in,
                              void* d_out, int out_size)
{
    (void)in_sizes; (void)n_in; (void)out_size;
    const float* inputs = (const float*)d_in[0];
    const float* W_ih   = (const float*)d_in[1];
    const float* W_hh   = (const float*)d_in[2];
    const float* b_ih   = (const float*)d_in[3];
    const float* b_hh   = (const float*)d_in[4];
    const int*   length = (const int*)d_in[5];
    float* out = (float*)d_out;

    cudaFuncSetAttribute(lstm_fused_kernel,
                         cudaFuncAttributeMaxDynamicSharedMemorySize, SM_TOTAL);

    __half *xhi, *xlo;
    cudaGetSymbolAddress((void**)&xhi, g_xhi);
    cudaGetSymbolAddress((void**)&xlo, g_xlo);

    const int nX4 = (BT * DIn) / 4;   // 4,194,304
    xsplit_kernel<<<(nX4 + 255) / 256, 256>>>(inputs, xhi, xlo, nX4);
    lstm_fused_kernel<<<NCTA, 256, SM_TOTAL>>>(W_hh, W_ih, b_ih, b_hh, length, out);
}